// round 10
// baseline (speedup 1.0000x reference)
#include <cuda_runtime.h>

// Fixed shapes
#define NB 16
#define NC 31
#define NHW 65536
#define NPAIR 496              // NC*(NC+1)/2
#define TILE_K 128

// K1 layout: gram blocks, copy blocks, then per-batch fallback/spin blocks
#define GRAM_CHUNKS 8          // per batch
#define GRAM_BLOCKS (NB * GRAM_CHUNKS)   // 128
#define SUB_CHUNK 512          // columns per gram block -> 4096-col subset
#define COPY_BLOCKS 2048
#define FB_BASE (GRAM_BLOCKS + COPY_BLOCKS)   // 2176
#define K1_BLOCKS (FB_BASE + NB)              // 2192
#define K1_THREADS 256

#define TOTAL4 (NB * NC * NHW / 4)   // float4 elements total = 8126464

// Scratch (device globals; reset by their consumers every replay)
__device__ float g_p1[NB * GRAM_CHUNKS * NPAIR];
__device__ int   g_cnt[NB];             // arrival ticket (reset by decide)
__device__ int   g_flag[NB];            // 1 => SVT provably identity
__device__ volatile int g_done[NB];     // decide published (reset by spin blk)

__device__ __forceinline__ int pair_index(int i, int j) {
    return i * NC - (i * (i - 1)) / 2 + (j - i);   // i <= j
}

// ---------------------------------------------------------------------------
// Single fused kernel:
//  blocks [0,128)        : subset-Gram partials; last arrival per batch does
//                          the Gershgorin decide, publishes g_flag + g_done.
//  blocks [128,2176)     : float4 streaming copy (identical to 68us path).
//  blocks [2176,2192)    : one per batch — spin until g_done[b], then exit if
//                          identity proven, else full SVT fallback in-place.
// The copy is unconditionally correct when the Gershgorin proof fires
// (sigma_min ~ 250 >> thr = 1e-4 for this data); the fallback overwrites it
// otherwise. Proof: lambda_min(G_full) >= lambda_min(G_subset) >= Gershgorin
// bound on the 4096-column subset Gram (adding columns adds a PSD term).
// ---------------------------------------------------------------------------
__global__ __launch_bounds__(K1_THREADS)
void fused_kernel(const float* __restrict__ x, float* __restrict__ out,
                  const float* __restrict__ soft_thr) {
    int t = threadIdx.x;

    if (blockIdx.x < GRAM_BLOCKS) {
        // ================= subset Gram + inline decide =================
        int g = blockIdx.x;
        int b = g >> 3;
        int chunk = g & 7;
        int k0 = chunk * SUB_CHUNK;

        __shared__ float xs[NC][TILE_K + 1];
        __shared__ int s_ticket;

        int pi0 = 0, pj0 = 0, pi1 = 0, pj1 = 0;
        {
            int tt = t, i = 0;
            while (tt >= NC - i) { tt -= (NC - i); i++; }
            pi0 = i; pj0 = i + tt;
        }
        int t1 = t + K1_THREADS;
        if (t1 < NPAIR) {
            int tt = t1, i = 0;
            while (tt >= NC - i) { tt -= (NC - i); i++; }
            pi1 = i; pj1 = i + tt;
        }

        const float* xb = x + (size_t)b * NC * NHW;
        float acc0 = 0.0f, acc1 = 0.0f;

        for (int kt = 0; kt < SUB_CHUNK; kt += TILE_K) {
            for (int idx = t; idx < NC * TILE_K; idx += K1_THREADS) {
                int c = idx >> 7, kk = idx & (TILE_K - 1);
                xs[c][kk] = xb[c * NHW + k0 + kt + kk];
            }
            __syncthreads();
            #pragma unroll 8
            for (int kk = 0; kk < TILE_K; kk++) {
                acc0 = fmaf(xs[pi0][kk], xs[pj0][kk], acc0);
                acc1 = fmaf(xs[pi1][kk], xs[pj1][kk], acc1);
            }
            __syncthreads();
        }

        g_p1[(b * GRAM_CHUNKS + chunk) * NPAIR + t] = acc0;
        if (t1 < NPAIR)
            g_p1[(b * GRAM_CHUNKS + chunk) * NPAIR + t1] = acc1;

        __threadfence();              // publish partials before ticket
        __syncthreads();
        if (t == 0)
            s_ticket = atomicAdd(&g_cnt[b], 1);
        __syncthreads();
        if (s_ticket == GRAM_CHUNKS - 1) {
            __threadfence();          // acquire other blocks' partials
            if (t < 32) {
                int lane = t;
                float bound = 1e30f;
                if (lane < NC) {
                    float diag = 0.0f, offs = 0.0f;
                    for (int j = 0; j < NC; j++) {
                        int i0 = lane < j ? lane : j;
                        int j0 = lane < j ? j : lane;
                        int tt = pair_index(i0, j0);
                        float gg = 0.0f;
                        #pragma unroll
                        for (int cch = 0; cch < GRAM_CHUNKS; cch++)
                            gg += g_p1[(b * GRAM_CHUNKS + cch) * NPAIR + tt];
                        if (j == lane) diag = gg; else offs += fabsf(gg);
                    }
                    bound = diag - offs;
                }
                for (int o = 16; o > 0; o >>= 1)
                    bound = fminf(bound, __shfl_xor_sync(0xffffffffu, bound, o));
                if (lane == 0) {
                    float thr = soft_thr[0];
                    g_flag[b] = (bound > thr * thr) ? 1 : 0;
                    g_cnt[b] = 0;             // reset for next replay
                    __threadfence();          // release flag before done
                    g_done[b] = 1;
                }
            }
        }
    } else if (blockIdx.x < FB_BASE) {
        // ======================= streaming copy =======================
        // TOTAL4 = 15.5 * span. 7 double-iterations cover spans [0,14);
        // tail loop covers the rest (every i < TOTAL4).
        const float4* src = (const float4*)x;
        float4*       dst = (float4*)out;
        const int span = COPY_BLOCKS * K1_THREADS;   // 524288
        int i = (blockIdx.x - GRAM_BLOCKS) * K1_THREADS + t;
        #pragma unroll 1
        for (int it = 0; it < 7; it++) {
            float4 v0 = __ldcs(src + i);
            float4 v1 = __ldcs(src + i + span);
            __stcs(dst + i, v0);
            __stcs(dst + i + span, v1);
            i += 2 * span;
        }
        #pragma unroll 1
        for (; i < TOTAL4; i += span) {
            float4 v = __ldcs(src + i);
            __stcs(dst + i, v);
        }
    } else {
        // ================= spin + gated fallback (per batch) ==========
        int b = blockIdx.x - FB_BASE;
        __shared__ int s_flag;

        if (t == 0) {
            while (g_done[b] == 0) { /* gram finishes in ~5us */ }
            __threadfence();          // acquire g_flag
            s_flag = g_flag[b];
            g_done[b] = 0;            // reset for next replay
        }
        __syncthreads();
        if (s_flag) return;           // identity proven -> copy stands

        // ---- rare path: full Gram, Jacobi, M = V diag(mask) V^T, M @ x ----
        __shared__ float xs[NC][TILE_K + 1];
        __shared__ float A[NC][NC + 2];
        __shared__ float V[NC][NC + 2];
        __shared__ float M[NC][NC + 1];
        __shared__ float mask[NC];

        const float* xb = x + (size_t)b * NC * NHW;

        int pi0 = 0, pj0 = 0, pi1 = 0, pj1 = 0;
        {
            int tt = t, i = 0;
            while (tt >= NC - i) { tt -= (NC - i); i++; }
            pi0 = i; pj0 = i + tt;
        }
        int t1 = t + K1_THREADS;
        if (t1 < NPAIR) {
            int tt = t1, i = 0;
            while (tt >= NC - i) { tt -= (NC - i); i++; }
            pi1 = i; pj1 = i + tt;
        }

        float acc0 = 0.0f, acc1 = 0.0f;
        for (int k0 = 0; k0 < NHW; k0 += TILE_K) {
            for (int idx = t; idx < NC * TILE_K; idx += K1_THREADS) {
                int c = idx >> 7, kk = idx & (TILE_K - 1);
                xs[c][kk] = xb[c * NHW + k0 + kk];
            }
            __syncthreads();
            #pragma unroll 8
            for (int kk = 0; kk < TILE_K; kk++) {
                acc0 = fmaf(xs[pi0][kk], xs[pj0][kk], acc0);
                acc1 = fmaf(xs[pi1][kk], xs[pj1][kk], acc1);
            }
            __syncthreads();
        }
        A[pi0][pj0] = acc0; A[pj0][pi0] = acc0;
        if (t1 < NPAIR) { A[pi1][pj1] = acc1; A[pj1][pi1] = acc1; }
        for (int idx = t; idx < NC * NC; idx += K1_THREADS) {
            int i = idx / NC, j = idx % NC;
            V[i][j] = (i == j) ? 1.0f : 0.0f;
        }
        __syncthreads();

        if (t < 32) {
            int lane = t;
            for (int sweep = 0; sweep < 12; sweep++) {
                for (int p = 0; p < NC - 1; p++) {
                    for (int q = p + 1; q < NC; q++) {
                        float apq = A[p][q];
                        float app = A[p][p], aqq = A[q][q];
                        if (fabsf(apq) <= 1e-12f * (fabsf(app) + fabsf(aqq)) + 1e-30f)
                            continue;
                        float theta = 0.5f * (aqq - app) / apq;
                        float tt2 = copysignf(1.0f, theta) /
                                    (fabsf(theta) + sqrtf(1.0f + theta * theta));
                        float c = rsqrtf(1.0f + tt2 * tt2);
                        float s = tt2 * c;
                        if (lane < NC) {
                            float Apk = A[p][lane], Aqk = A[q][lane];
                            A[p][lane] = c * Apk - s * Aqk;
                            A[q][lane] = s * Apk + c * Aqk;
                        }
                        __syncwarp();
                        if (lane < NC) {
                            float Akp = A[lane][p], Akq = A[lane][q];
                            A[lane][p] = c * Akp - s * Akq;
                            A[lane][q] = s * Akp + c * Akq;
                            float Vkp = V[lane][p], Vkq = V[lane][q];
                            V[lane][p] = c * Vkp - s * Vkq;
                            V[lane][q] = s * Vkp + c * Vkq;
                        }
                        __syncwarp();
                    }
                }
            }
            if (lane < NC) {
                float sv = sqrtf(fmaxf(A[lane][lane], 0.0f));
                mask[lane] = (sv > soft_thr[0]) ? 1.0f : 0.0f;
            }
            __syncwarp();
            if (lane < NC) {
                for (int r = 0; r < NC; r++) {
                    float m = 0.0f;
                    for (int i = 0; i < NC; i++)
                        m += mask[i] * V[r][i] * V[lane][i];
                    M[r][lane] = m;
                }
            }
        }
        __syncthreads();

        float* ob = out + (size_t)b * NC * NHW;
        for (int k = t; k < NHW; k += K1_THREADS) {
            float xv[NC];
            #pragma unroll
            for (int j = 0; j < NC; j++) xv[j] = xb[(size_t)j * NHW + k];
            #pragma unroll 1
            for (int c = 0; c < NC; c++) {
                float a = 0.0f;
                #pragma unroll
                for (int j = 0; j < NC; j++) a = fmaf(M[c][j], xv[j], a);
                ob[(size_t)c * NHW + k] = a;
            }
        }
    }
}

extern "C" void kernel_launch(void* const* d_in, const int* in_sizes, int n_in,
                              void* d_out, int out_size) {
    // Identify inputs by size (soft_thr has 1 element)
    const float* x   = (const float*)d_in[0];
    const float* thr = (const float*)d_in[1];
    if (n_in >= 2) {
        if (in_sizes[0] == 1) { thr = (const float*)d_in[0]; x = (const float*)d_in[1]; }
        else                  { x  = (const float*)d_in[0]; thr = (const float*)d_in[1]; }
    }
    float* out = (float*)d_out;

    // One fused launch: speculative copy + subset-Gram + decide + gated fallback
    fused_kernel<<<K1_BLOCKS, K1_THREADS>>>(x, out, thr);
}

// round 11
// speedup vs baseline: 1.0255x; 1.0255x over previous
#include <cuda_runtime.h>

// Fixed shapes
#define NB 16
#define NC 31
#define NHW 65536
#define NPAIR 496              // NC*(NC+1)/2
#define TILE_K 128

// K1 layout: gram blocks, copy blocks, then per-batch fallback/spin blocks
#define GRAM_CHUNKS 8          // per batch
#define GRAM_BLOCKS (NB * GRAM_CHUNKS)   // 128
#define SUB_CHUNK 512          // columns per gram block -> 4096-col subset
#define COPY_BLOCKS 2048
#define FB_BASE (GRAM_BLOCKS + COPY_BLOCKS)   // 2176
#define K1_BLOCKS (FB_BASE + NB)              // 2192
#define K1_THREADS 256

#define TOTAL4 (NB * NC * NHW / 4)   // float4 elements total = 8126464

// Scratch (device globals; reset by their consumers every replay)
__device__ float g_p1[NB * GRAM_CHUNKS * NPAIR];
__device__ int   g_cnt[NB];             // arrival ticket (reset by decide)
__device__ int   g_flag[NB];            // 1 => SVT provably identity
__device__ volatile int g_done[NB];     // decide published (reset by spin blk)

__device__ __forceinline__ int pair_index(int i, int j) {
    return i * NC - (i * (i - 1)) / 2 + (j - i);   // i <= j
}

// ---------------------------------------------------------------------------
// Single fused kernel:
//  blocks [0,128)        : subset-Gram partials; last arrival per batch does
//                          the Gershgorin decide, publishes g_flag + g_done.
//  blocks [128,2176)     : float4 streaming copy (identical to 68us path).
//  blocks [2176,2192)    : one per batch — spin until g_done[b], then exit if
//                          identity proven, else full SVT fallback in-place.
// The copy is unconditionally correct when the Gershgorin proof fires
// (sigma_min ~ 250 >> thr = 1e-4 for this data); the fallback overwrites it
// otherwise. Proof: lambda_min(G_full) >= lambda_min(G_subset) >= Gershgorin
// bound on the 4096-column subset Gram (adding columns adds a PSD term).
// ---------------------------------------------------------------------------
__global__ __launch_bounds__(K1_THREADS)
void fused_kernel(const float* __restrict__ x, float* __restrict__ out,
                  const float* __restrict__ soft_thr) {
    int t = threadIdx.x;

    if (blockIdx.x < GRAM_BLOCKS) {
        // ================= subset Gram + inline decide =================
        int g = blockIdx.x;
        int b = g >> 3;
        int chunk = g & 7;
        int k0 = chunk * SUB_CHUNK;

        __shared__ float xs[NC][TILE_K + 1];
        __shared__ int s_ticket;

        int pi0 = 0, pj0 = 0, pi1 = 0, pj1 = 0;
        {
            int tt = t, i = 0;
            while (tt >= NC - i) { tt -= (NC - i); i++; }
            pi0 = i; pj0 = i + tt;
        }
        int t1 = t + K1_THREADS;
        if (t1 < NPAIR) {
            int tt = t1, i = 0;
            while (tt >= NC - i) { tt -= (NC - i); i++; }
            pi1 = i; pj1 = i + tt;
        }

        const float* xb = x + (size_t)b * NC * NHW;
        float acc0 = 0.0f, acc1 = 0.0f;

        for (int kt = 0; kt < SUB_CHUNK; kt += TILE_K) {
            for (int idx = t; idx < NC * TILE_K; idx += K1_THREADS) {
                int c = idx >> 7, kk = idx & (TILE_K - 1);
                xs[c][kk] = xb[c * NHW + k0 + kt + kk];
            }
            __syncthreads();
            #pragma unroll 8
            for (int kk = 0; kk < TILE_K; kk++) {
                acc0 = fmaf(xs[pi0][kk], xs[pj0][kk], acc0);
                acc1 = fmaf(xs[pi1][kk], xs[pj1][kk], acc1);
            }
            __syncthreads();
        }

        g_p1[(b * GRAM_CHUNKS + chunk) * NPAIR + t] = acc0;
        if (t1 < NPAIR)
            g_p1[(b * GRAM_CHUNKS + chunk) * NPAIR + t1] = acc1;

        __threadfence();              // publish partials before ticket
        __syncthreads();
        if (t == 0)
            s_ticket = atomicAdd(&g_cnt[b], 1);
        __syncthreads();
        if (s_ticket == GRAM_CHUNKS - 1) {
            __threadfence();          // acquire other blocks' partials
            if (t < 32) {
                int lane = t;
                float bound = 1e30f;
                if (lane < NC) {
                    float diag = 0.0f, offs = 0.0f;
                    for (int j = 0; j < NC; j++) {
                        int i0 = lane < j ? lane : j;
                        int j0 = lane < j ? j : lane;
                        int tt = pair_index(i0, j0);
                        float gg = 0.0f;
                        #pragma unroll
                        for (int cch = 0; cch < GRAM_CHUNKS; cch++)
                            gg += g_p1[(b * GRAM_CHUNKS + cch) * NPAIR + tt];
                        if (j == lane) diag = gg; else offs += fabsf(gg);
                    }
                    bound = diag - offs;
                }
                for (int o = 16; o > 0; o >>= 1)
                    bound = fminf(bound, __shfl_xor_sync(0xffffffffu, bound, o));
                if (lane == 0) {
                    float thr = soft_thr[0];
                    g_flag[b] = (bound > thr * thr) ? 1 : 0;
                    g_cnt[b] = 0;             // reset for next replay
                    __threadfence();          // release flag before done
                    g_done[b] = 1;
                }
            }
        }
    } else if (blockIdx.x < FB_BASE) {
        // ======================= streaming copy =======================
        // TOTAL4 = 15.5 * span. 7 double-iterations cover spans [0,14);
        // tail loop covers the rest (every i < TOTAL4).
        const float4* src = (const float4*)x;
        float4*       dst = (float4*)out;
        const int span = COPY_BLOCKS * K1_THREADS;   // 524288
        int i = (blockIdx.x - GRAM_BLOCKS) * K1_THREADS + t;
        #pragma unroll 1
        for (int it = 0; it < 7; it++) {
            float4 v0 = __ldcs(src + i);
            float4 v1 = __ldcs(src + i + span);
            __stcs(dst + i, v0);
            __stcs(dst + i + span, v1);
            i += 2 * span;
        }
        #pragma unroll 1
        for (; i < TOTAL4; i += span) {
            float4 v = __ldcs(src + i);
            __stcs(dst + i, v);
        }
    } else {
        // ================= spin + gated fallback (per batch) ==========
        int b = blockIdx.x - FB_BASE;
        __shared__ int s_flag;

        if (t == 0) {
            while (g_done[b] == 0) { /* gram finishes in ~5us */ }
            __threadfence();          // acquire g_flag
            s_flag = g_flag[b];
            g_done[b] = 0;            // reset for next replay
        }
        __syncthreads();
        if (s_flag) return;           // identity proven -> copy stands

        // ---- rare path: full Gram, Jacobi, M = V diag(mask) V^T, M @ x ----
        __shared__ float xs[NC][TILE_K + 1];
        __shared__ float A[NC][NC + 2];
        __shared__ float V[NC][NC + 2];
        __shared__ float M[NC][NC + 1];
        __shared__ float mask[NC];

        const float* xb = x + (size_t)b * NC * NHW;

        int pi0 = 0, pj0 = 0, pi1 = 0, pj1 = 0;
        {
            int tt = t, i = 0;
            while (tt >= NC - i) { tt -= (NC - i); i++; }
            pi0 = i; pj0 = i + tt;
        }
        int t1 = t + K1_THREADS;
        if (t1 < NPAIR) {
            int tt = t1, i = 0;
            while (tt >= NC - i) { tt -= (NC - i); i++; }
            pi1 = i; pj1 = i + tt;
        }

        float acc0 = 0.0f, acc1 = 0.0f;
        for (int k0 = 0; k0 < NHW; k0 += TILE_K) {
            for (int idx = t; idx < NC * TILE_K; idx += K1_THREADS) {
                int c = idx >> 7, kk = idx & (TILE_K - 1);
                xs[c][kk] = xb[c * NHW + k0 + kk];
            }
            __syncthreads();
            #pragma unroll 8
            for (int kk = 0; kk < TILE_K; kk++) {
                acc0 = fmaf(xs[pi0][kk], xs[pj0][kk], acc0);
                acc1 = fmaf(xs[pi1][kk], xs[pj1][kk], acc1);
            }
            __syncthreads();
        }
        A[pi0][pj0] = acc0; A[pj0][pi0] = acc0;
        if (t1 < NPAIR) { A[pi1][pj1] = acc1; A[pj1][pi1] = acc1; }
        for (int idx = t; idx < NC * NC; idx += K1_THREADS) {
            int i = idx / NC, j = idx % NC;
            V[i][j] = (i == j) ? 1.0f : 0.0f;
        }
        __syncthreads();

        if (t < 32) {
            int lane = t;
            for (int sweep = 0; sweep < 12; sweep++) {
                for (int p = 0; p < NC - 1; p++) {
                    for (int q = p + 1; q < NC; q++) {
                        float apq = A[p][q];
                        float app = A[p][p], aqq = A[q][q];
                        if (fabsf(apq) <= 1e-12f * (fabsf(app) + fabsf(aqq)) + 1e-30f)
                            continue;
                        float theta = 0.5f * (aqq - app) / apq;
                        float tt2 = copysignf(1.0f, theta) /
                                    (fabsf(theta) + sqrtf(1.0f + theta * theta));
                        float c = rsqrtf(1.0f + tt2 * tt2);
                        float s = tt2 * c;
                        if (lane < NC) {
                            float Apk = A[p][lane], Aqk = A[q][lane];
                            A[p][lane] = c * Apk - s * Aqk;
                            A[q][lane] = s * Apk + c * Aqk;
                        }
                        __syncwarp();
                        if (lane < NC) {
                            float Akp = A[lane][p], Akq = A[lane][q];
                            A[lane][p] = c * Akp - s * Akq;
                            A[lane][q] = s * Akp + c * Akq;
                            float Vkp = V[lane][p], Vkq = V[lane][q];
                            V[lane][p] = c * Vkp - s * Vkq;
                            V[lane][q] = s * Vkp + c * Vkq;
                        }
                        __syncwarp();
                    }
                }
            }
            if (lane < NC) {
                float sv = sqrtf(fmaxf(A[lane][lane], 0.0f));
                mask[lane] = (sv > soft_thr[0]) ? 1.0f : 0.0f;
            }
            __syncwarp();
            if (lane < NC) {
                for (int r = 0; r < NC; r++) {
                    float m = 0.0f;
                    for (int i = 0; i < NC; i++)
                        m += mask[i] * V[r][i] * V[lane][i];
                    M[r][lane] = m;
                }
            }
        }
        __syncthreads();

        float* ob = out + (size_t)b * NC * NHW;
        for (int k = t; k < NHW; k += K1_THREADS) {
            float xv[NC];
            #pragma unroll
            for (int j = 0; j < NC; j++) xv[j] = xb[(size_t)j * NHW + k];
            #pragma unroll 1
            for (int c = 0; c < NC; c++) {
                float a = 0.0f;
                #pragma unroll
                for (int j = 0; j < NC; j++) a = fmaf(M[c][j], xv[j], a);
                ob[(size_t)c * NHW + k] = a;
            }
        }
    }
}

extern "C" void kernel_launch(void* const* d_in, const int* in_sizes, int n_in,
                              void* d_out, int out_size) {
    // Identify inputs by size (soft_thr has 1 element)
    const float* x   = (const float*)d_in[0];
    const float* thr = (const float*)d_in[1];
    if (n_in >= 2) {
        if (in_sizes[0] == 1) { thr = (const float*)d_in[0]; x = (const float*)d_in[1]; }
        else                  { x  = (const float*)d_in[0]; thr = (const float*)d_in[1]; }
    }
    float* out = (float*)d_out;

    // One fused launch: speculative copy + subset-Gram + decide + gated fallback
    fused_kernel<<<K1_BLOCKS, K1_THREADS>>>(x, out, thr);
}